// round 2
// baseline (speedup 1.0000x reference)
#include <cuda_runtime.h>
#include <stdint.h>

#define ATTN_SCALE 0.08838834764831845f  // 128^-0.5

// ---------------------------------------------------------------------------
// helpers
// ---------------------------------------------------------------------------
__device__ __forceinline__ uint32_t f2tf(float x) {
    uint32_t r;
    asm("cvt.rna.tf32.f32 %0, %1;" : "=r"(r) : "f"(x));
    return r;
}

// D += A*B  (m16n8k8 tf32, fp32 accum). d aliases c.
__device__ __forceinline__ void mma8(float* d, const uint32_t* a, const uint32_t* b) {
    asm volatile(
        "mma.sync.aligned.m16n8k8.row.col.f32.tf32.tf32.f32 "
        "{%0,%1,%2,%3}, {%4,%5,%6,%7}, {%8,%9}, {%0,%1,%2,%3};\n"
        : "+f"(d[0]), "+f"(d[1]), "+f"(d[2]), "+f"(d[3])
        : "r"(a[0]), "r"(a[1]), "r"(a[2]), "r"(a[3]), "r"(b[0]), "r"(b[1]));
}

__device__ __forceinline__ void cpa16(void* s, const void* g) {
    uint32_t sa = (uint32_t)__cvta_generic_to_shared(s);
    asm volatile("cp.async.cg.shared.global [%0], [%1], 16;\n" :: "r"(sa), "l"(g));
}
__device__ __forceinline__ void cp_commit() { asm volatile("cp.async.commit_group;\n"); }
template <int N>
__device__ __forceinline__ void cp_wait() { asm volatile("cp.async.wait_group %0;\n" :: "n"(N)); }

// ---------------------------------------------------------------------------
// GEMM: C[M,N] = A[M,K] @ W[N,K]^T + bias[N]   (tf32 tensor cores)
// block tile 128x128, k-tile 32, 256 threads (8 warps, 2x4), double-buffered
// ---------------------------------------------------------------------------
#define GPAD 36  // 32 data + 4 pad floats per smem row -> conflict-free frags

__global__ __launch_bounds__(256) void gemm_tf32(
    const float* __restrict__ A, const float* __restrict__ W,
    const float* __restrict__ bias, float* __restrict__ C,
    int M, int N, int K)
{
    extern __shared__ float sm[];
    float* As = sm;                 // [2][128*GPAD]
    float* Bs = sm + 2 * 128 * GPAD;

    const int tid  = threadIdx.x;
    const int bm   = blockIdx.y * 128;
    const int bn   = blockIdx.x * 128;
    const int w    = tid >> 5, lane = tid & 31;
    const int qid  = lane >> 2, qt = lane & 3;
    const int wm   = (w >> 2) * 64;   // 0 / 64
    const int wn   = (w & 3) * 32;    // 0..96

    float acc[4][4][4];
#pragma unroll
    for (int i = 0; i < 4; i++)
#pragma unroll
        for (int j = 0; j < 4; j++)
#pragma unroll
            for (int r = 0; r < 4; r++) acc[i][j][r] = 0.f;

    const int KT = K >> 5;

    // tile loader: 128 rows x 32 cols per operand -> 1024 16B chunks each
    auto issue = [&](int buf, int kb) {
#pragma unroll
        for (int i = 0; i < 4; i++) {
            int id = tid + i * 256;
            int r = id >> 3, c = (id & 7) << 2;
            cpa16(&As[buf * 128 * GPAD + r * GPAD + c], A + (size_t)(bm + r) * K + kb + c);
            cpa16(&Bs[buf * 128 * GPAD + r * GPAD + c], W + (size_t)(bn + r) * K + kb + c);
        }
        cp_commit();
    };

    issue(0, 0);
    for (int t = 0; t < KT; t++) {
        if (t + 1 < KT) { issue((t + 1) & 1, (t + 1) << 5); cp_wait<1>(); }
        else            { cp_wait<0>(); }
        __syncthreads();

        const float* a  = &As[(t & 1) * 128 * GPAD];
        const float* bs = &Bs[(t & 1) * 128 * GPAD];
#pragma unroll
        for (int ks = 0; ks < 4; ks++) {
            const int k0 = ks * 8;
            uint32_t af[4][4], bf[4][2];
#pragma unroll
            for (int mt = 0; mt < 4; mt++) {
                int r = wm + mt * 16 + qid;
                af[mt][0] = f2tf(a[r * GPAD + k0 + qt]);
                af[mt][1] = f2tf(a[(r + 8) * GPAD + k0 + qt]);
                af[mt][2] = f2tf(a[r * GPAD + k0 + qt + 4]);
                af[mt][3] = f2tf(a[(r + 8) * GPAD + k0 + qt + 4]);
            }
#pragma unroll
            for (int nt = 0; nt < 4; nt++) {
                int cn = wn + nt * 8 + qid;
                bf[nt][0] = f2tf(bs[cn * GPAD + k0 + qt]);
                bf[nt][1] = f2tf(bs[cn * GPAD + k0 + qt + 4]);
            }
#pragma unroll
            for (int mt = 0; mt < 4; mt++)
#pragma unroll
                for (int nt = 0; nt < 4; nt++)
                    mma8(acc[mt][nt], af[mt], bf[nt]);
        }
        __syncthreads();
    }

    // epilogue
#pragma unroll
    for (int mt = 0; mt < 4; mt++) {
        int r = bm + wm + mt * 16 + qid;
#pragma unroll
        for (int nt = 0; nt < 4; nt++) {
            int c0 = bn + wn + nt * 8 + 2 * qt;
            float b0 = bias[c0], b1 = bias[c0 + 1];
            *(float2*)&C[(size_t)r * N + c0] =
                make_float2(acc[mt][nt][0] + b0, acc[mt][nt][1] + b1);
            *(float2*)&C[(size_t)(r + 8) * N + c0] =
                make_float2(acc[mt][nt][2] + b0, acc[mt][nt][3] + b1);
        }
    }
}

// ---------------------------------------------------------------------------
// Flash attention: one block per (b,h). 256 threads, 8 warps (2x4).
// Streams 129 chunks of 32 keys (128 from cache + 1 from new K/V in qkv buf).
// Online softmax; tf32 MMAs; cp.async double-buffered K/V.
// ---------------------------------------------------------------------------
#define APAD 132  // 128 data + 4 pad
#define PPAD 36

__global__ __launch_bounds__(256, 2) void attn_tf32(
    const float* __restrict__ qkv,   // (512, 6144) = (b*32+t, [q|k|v] h dk)
    const float* __restrict__ kc,    // (B,H,S,DK)
    const float* __restrict__ vc,
    float* __restrict__ o)           // (512, 2048) = (b*32+t, h*128+dk)
{
    extern __shared__ float sm[];
    float* qs = sm;                          // 32*APAD
    float* Ks = sm + 32 * APAD;              // 2 * 32*APAD
    float* Vs = sm + 3 * 32 * APAD;          // 2 * 32*APAD
    float* Ps = sm + 5 * 32 * APAD;          // 32*PPAD
    float* ms = Ps + 32 * PPAD;              // 32
    float* ls = ms + 32;                     // 32
    float* cs = ms + 64;                     // 32

    const int bh = blockIdx.x, b = bh >> 4, h = bh & 15;
    const int tid = threadIdx.x, w = tid >> 5, lane = tid & 31;
    const int qid = lane >> 2, qt = lane & 3;
    const int wm = (w >> 2) << 4;  // 0 / 16
    const int wn = w & 3;          // 0..3

    // load + scale q, convert to tf32 in smem
#pragma unroll
    for (int i = 0; i < 4; i++) {
        int id = tid + i * 256;
        int r = id >> 5, c = (id & 31) << 2;
        float4 v = *(const float4*)(qkv + (size_t)(b * 32 + r) * 6144 + h * 128 + c);
        qs[r * APAD + c + 0] = __uint_as_float(f2tf(v.x * ATTN_SCALE));
        qs[r * APAD + c + 1] = __uint_as_float(f2tf(v.y * ATTN_SCALE));
        qs[r * APAD + c + 2] = __uint_as_float(f2tf(v.z * ATTN_SCALE));
        qs[r * APAD + c + 3] = __uint_as_float(f2tf(v.w * ATTN_SCALE));
    }
    if (tid < 32) { ms[tid] = -1e30f; ls[tid] = 0.f; }
    __syncthreads();

    // hold warp's q fragments (its 16-row mtile, full K=128) in registers
    uint32_t qf[16][4];
#pragma unroll
    for (int ks = 0; ks < 16; ks++) {
        int r = wm + qid, k0 = ks * 8;
        qf[ks][0] = __float_as_uint(qs[r * APAD + k0 + qt]);
        qf[ks][1] = __float_as_uint(qs[(r + 8) * APAD + k0 + qt]);
        qf[ks][2] = __float_as_uint(qs[r * APAD + k0 + qt + 4]);
        qf[ks][3] = __float_as_uint(qs[(r + 8) * APAD + k0 + qt + 4]);
    }

    float acc[4][4];
#pragma unroll
    for (int i = 0; i < 4; i++)
#pragma unroll
        for (int j = 0; j < 4; j++) acc[i][j] = 0.f;

    const float* kb0 = kc + (size_t)bh * 4096 * 128;
    const float* vb0 = vc + (size_t)bh * 4096 * 128;

    auto load_chunk = [&](int buf, int c) {
        float* kd = &Ks[buf * 32 * APAD];
        float* vd = &Vs[buf * 32 * APAD];
        if (c < 128) {
            const float* kp = kb0 + (size_t)c * 32 * 128;
            const float* vp = vb0 + (size_t)c * 32 * 128;
#pragma unroll
            for (int i = 0; i < 4; i++) {
                int id = tid + i * 256;
                int r = id >> 5, cc = (id & 31) << 2;
                cpa16(&kd[r * APAD + cc], kp + r * 128 + cc);
                cpa16(&vd[r * APAD + cc], vp + r * 128 + cc);
            }
        } else {  // new k/v from qkv projection buffer
#pragma unroll
            for (int i = 0; i < 4; i++) {
                int id = tid + i * 256;
                int r = id >> 5, cc = (id & 31) << 2;
                const float* base = qkv + (size_t)(b * 32 + r) * 6144 + h * 128 + cc;
                cpa16(&kd[r * APAD + cc], base + 2048);
                cpa16(&vd[r * APAD + cc], base + 4096);
            }
        }
        cp_commit();
    };

    load_chunk(0, 0);
    for (int c = 0; c < 129; c++) {
        const int buf = c & 1;
        if (c + 1 < 129) { load_chunk(buf ^ 1, c + 1); cp_wait<1>(); }
        else             { cp_wait<0>(); }
        __syncthreads();

        // ---- Phase A: scores (32x32) — warp: rows wm..wm+15, cols wn*8..+7
        const float* kd = &Ks[buf * 32 * APAD];
        float sc[4] = {0.f, 0.f, 0.f, 0.f};
        const int sl = wn * 8 + qid;
#pragma unroll
        for (int ks = 0; ks < 16; ks++) {
            uint32_t bf[2];
            bf[0] = f2tf(kd[sl * APAD + ks * 8 + qt]);
            bf[1] = f2tf(kd[sl * APAD + ks * 8 + qt + 4]);
            mma8(sc, qf[ks], bf);
        }
        {
            int pr = wm + qid, pc = wn * 8 + 2 * qt;
            Ps[pr * PPAD + pc]           = sc[0];
            Ps[pr * PPAD + pc + 1]       = sc[1];
            Ps[(pr + 8) * PPAD + pc]     = sc[2];
            Ps[(pr + 8) * PPAD + pc + 1] = sc[3];
        }
        __syncthreads();

        // ---- Phase B: online softmax (8 threads per row)
        {
            int row = tid >> 3, l8 = tid & 7;
            float4 p = *(float4*)&Ps[row * PPAD + l8 * 4];
            float mx = fmaxf(fmaxf(p.x, p.y), fmaxf(p.z, p.w));
            mx = fmaxf(mx, __shfl_xor_sync(0xffffffffu, mx, 1));
            mx = fmaxf(mx, __shfl_xor_sync(0xffffffffu, mx, 2));
            mx = fmaxf(mx, __shfl_xor_sync(0xffffffffu, mx, 4));
            float mo = ms[row];
            float mn = fmaxf(mo, mx);
            float corr = __expf(mo - mn);
            p.x = __expf(p.x - mn);
            p.y = __expf(p.y - mn);
            p.z = __expf(p.z - mn);
            p.w = __expf(p.w - mn);
            float s = p.x + p.y + p.z + p.w;
            s += __shfl_xor_sync(0xffffffffu, s, 1);
            s += __shfl_xor_sync(0xffffffffu, s, 2);
            s += __shfl_xor_sync(0xffffffffu, s, 4);
            if (l8 == 0) { ms[row] = mn; ls[row] = ls[row] * corr + s; cs[row] = corr; }
            p.x = __uint_as_float(f2tf(p.x));
            p.y = __uint_as_float(f2tf(p.y));
            p.z = __uint_as_float(f2tf(p.z));
            p.w = __uint_as_float(f2tf(p.w));
            *(float4*)&Ps[row * PPAD + l8 * 4] = p;
        }
        __syncthreads();

        // ---- Phase C: rescale accumulators + P@V — warp cols wn*32..+31
        const float* vd = &Vs[buf * 32 * APAD];
        float c0 = cs[wm + qid], c1 = cs[wm + qid + 8];
#pragma unroll
        for (int nt = 0; nt < 4; nt++) {
            acc[nt][0] *= c0; acc[nt][1] *= c0;
            acc[nt][2] *= c1; acc[nt][3] *= c1;
        }
#pragma unroll
        for (int ks = 0; ks < 4; ks++) {
            uint32_t pf[4];
            int r = wm + qid, k0 = ks * 8;
            pf[0] = __float_as_uint(Ps[r * PPAD + k0 + qt]);
            pf[1] = __float_as_uint(Ps[(r + 8) * PPAD + k0 + qt]);
            pf[2] = __float_as_uint(Ps[r * PPAD + k0 + qt + 4]);
            pf[3] = __float_as_uint(Ps[(r + 8) * PPAD + k0 + qt + 4]);
#pragma unroll
            for (int nt = 0; nt < 4; nt++) {
                uint32_t vf[2];
                int cn = wn * 32 + nt * 8 + qid;
                vf[0] = f2tf(vd[(k0 + qt) * APAD + cn]);
                vf[1] = f2tf(vd[(k0 + qt + 4) * APAD + cn]);
                mma8(acc[nt], pf, vf);
            }
        }
        __syncthreads();
    }

    // epilogue: divide by l, write (b,t,h,dk)
    float inv0 = 1.f / ls[wm + qid];
    float inv1 = 1.f / ls[wm + qid + 8];
#pragma unroll
    for (int nt = 0; nt < 4; nt++) {
        int r = wm + qid, cn = wn * 32 + nt * 8 + 2 * qt;
        size_t o0 = (size_t)(b * 32 + r) * 2048 + h * 128 + cn;
        size_t o1 = (size_t)(b * 32 + r + 8) * 2048 + h * 128 + cn;
        *(float2*)&o[o0] = make_float2(acc[nt][0] * inv0, acc[nt][1] * inv0);
        *(float2*)&o[o1] = make_float2(acc[nt][2] * inv1, acc[nt][3] * inv1);
    }
}

// ---------------------------------------------------------------------------
// scratch + launch
// ---------------------------------------------------------------------------
__device__ float g_qkv[512 * 6144];   // (b*32+t, 3*2048)
__device__ float g_attn[512 * 2048];  // (b*32+t, h*128+dk)

extern "C" void kernel_launch(void* const* d_in, const int* in_sizes, int n_in,
                              void* d_out, int out_size)
{
    const float* x    = (const float*)d_in[0];
    const float* kc   = (const float*)d_in[1];
    const float* vc   = (const float*)d_in[2];
    const float* qkvw = (const float*)d_in[3];
    const float* qkvb = (const float*)d_in[4];
    const float* outw = (const float*)d_in[5];
    const float* outb = (const float*)d_in[6];
    float* out = (float*)d_out;

    float *qkvbuf, *attnbuf;
    cudaGetSymbolAddress((void**)&qkvbuf, g_qkv);
    cudaGetSymbolAddress((void**)&attnbuf, g_attn);

    const int GEMM_SMEM = 2 * 2 * 128 * GPAD * sizeof(float);            // 73728 B
    const int ATTN_SMEM = (5 * 32 * APAD + 32 * PPAD + 96) * sizeof(float);  // 89472 B
    cudaFuncSetAttribute(gemm_tf32, cudaFuncAttributeMaxDynamicSharedMemorySize, GEMM_SMEM);
    cudaFuncSetAttribute(attn_tf32, cudaFuncAttributeMaxDynamicSharedMemorySize, ATTN_SMEM);

    // 1) fused QKV projection: (512x2048)@(6144x2048)^T + b -> g_qkv
    gemm_tf32<<<dim3(48, 4), 256, GEMM_SMEM>>>(x, qkvw, qkvb, qkvbuf, 512, 6144, 2048);
    // 2) attention over cache + new kv
    attn_tf32<<<256, 256, ATTN_SMEM>>>(qkvbuf, kc, vc, attnbuf);
    // 3) output projection: (512x2048)@(2048x2048)^T + b -> d_out
    gemm_tf32<<<dim3(16, 4), 256, GEMM_SMEM>>>(attnbuf, outw, outb, out, 512, 2048, 2048);
}

// round 3
// speedup vs baseline: 1.2043x; 1.2043x over previous
#include <cuda_runtime.h>
#include <stdint.h>

#define ATTN_SCALE 0.08838834764831845f  // 128^-0.5

// ---------------------------------------------------------------------------
// helpers
// ---------------------------------------------------------------------------
__device__ __forceinline__ uint32_t f2tf(float x) {
    uint32_t r;
    asm("cvt.rna.tf32.f32 %0, %1;" : "=r"(r) : "f"(x));
    return r;
}

// D += A*B  (m16n8k8 tf32, fp32 accum). d aliases c.
__device__ __forceinline__ void mma8(float* d, const uint32_t* a, const uint32_t* b) {
    asm volatile(
        "mma.sync.aligned.m16n8k8.row.col.f32.tf32.tf32.f32 "
        "{%0,%1,%2,%3}, {%4,%5,%6,%7}, {%8,%9}, {%0,%1,%2,%3};\n"
        : "+f"(d[0]), "+f"(d[1]), "+f"(d[2]), "+f"(d[3])
        : "r"(a[0]), "r"(a[1]), "r"(a[2]), "r"(a[3]), "r"(b[0]), "r"(b[1]));
}

__device__ __forceinline__ void cpa16(void* s, const void* g) {
    uint32_t sa = (uint32_t)__cvta_generic_to_shared(s);
    asm volatile("cp.async.cg.shared.global [%0], [%1], 16;\n" :: "r"(sa), "l"(g));
}
__device__ __forceinline__ void cp_commit() { asm volatile("cp.async.commit_group;\n"); }
template <int N>
__device__ __forceinline__ void cp_wait() { asm volatile("cp.async.wait_group %0;\n" :: "n"(N)); }

// ---------------------------------------------------------------------------
// GEMM: C[M,N] = A[M,K] @ W[N,K]^T + bias[N]   (tf32 tensor cores)
// block tile 64x128, k-tile 32, 256 threads (8 warps 2x4, warp tile 32x32),
// double-buffered cp.async. Small tiles -> ~75 regs -> 3 CTAs/SM.
// ---------------------------------------------------------------------------
#define GPAD 36  // 32 data + 4 pad floats per smem row -> conflict-free frags

__global__ __launch_bounds__(256, 3) void gemm_tf32(
    const float* __restrict__ A, const float* __restrict__ W,
    const float* __restrict__ bias, float* __restrict__ C,
    int M, int N, int K)
{
    extern __shared__ float sm[];
    float* As = sm;                  // [2][64*GPAD]
    float* Bs = sm + 2 * 64 * GPAD;  // [2][128*GPAD]

    const int tid  = threadIdx.x;
    const int bm   = blockIdx.y * 64;
    const int bn   = blockIdx.x * 128;
    const int w    = tid >> 5, lane = tid & 31;
    const int qid  = lane >> 2, qt = lane & 3;
    const int wm   = (w >> 2) * 32;   // 0 / 32
    const int wn   = (w & 3) * 32;    // 0..96

    float acc[2][4][4];
#pragma unroll
    for (int i = 0; i < 2; i++)
#pragma unroll
        for (int j = 0; j < 4; j++)
#pragma unroll
            for (int r = 0; r < 4; r++) acc[i][j][r] = 0.f;

    const int KT = K >> 5;

    auto issue = [&](int buf, int kb) {
#pragma unroll
        for (int i = 0; i < 2; i++) {  // A: 64 rows x 32 cols
            int id = tid + i * 256;
            int r = id >> 3, c = (id & 7) << 2;
            cpa16(&As[buf * 64 * GPAD + r * GPAD + c], A + (size_t)(bm + r) * K + kb + c);
        }
#pragma unroll
        for (int i = 0; i < 4; i++) {  // B: 128 rows x 32 cols
            int id = tid + i * 256;
            int r = id >> 3, c = (id & 7) << 2;
            cpa16(&Bs[buf * 128 * GPAD + r * GPAD + c], W + (size_t)(bn + r) * K + kb + c);
        }
        cp_commit();
    };

    issue(0, 0);
    for (int t = 0; t < KT; t++) {
        if (t + 1 < KT) { issue((t + 1) & 1, (t + 1) << 5); cp_wait<1>(); }
        else            { cp_wait<0>(); }
        __syncthreads();

        const float* a  = &As[(t & 1) * 64 * GPAD];
        const float* bs = &Bs[(t & 1) * 128 * GPAD];
#pragma unroll
        for (int ks = 0; ks < 4; ks++) {
            const int k0 = ks * 8;
            uint32_t af[2][4], bf[4][2];
#pragma unroll
            for (int mt = 0; mt < 2; mt++) {
                int r = wm + mt * 16 + qid;
                af[mt][0] = f2tf(a[r * GPAD + k0 + qt]);
                af[mt][1] = f2tf(a[(r + 8) * GPAD + k0 + qt]);
                af[mt][2] = f2tf(a[r * GPAD + k0 + qt + 4]);
                af[mt][3] = f2tf(a[(r + 8) * GPAD + k0 + qt + 4]);
            }
#pragma unroll
            for (int nt = 0; nt < 4; nt++) {
                int cn = wn + nt * 8 + qid;
                bf[nt][0] = f2tf(bs[cn * GPAD + k0 + qt]);
                bf[nt][1] = f2tf(bs[cn * GPAD + k0 + qt + 4]);
            }
#pragma unroll
            for (int mt = 0; mt < 2; mt++)
#pragma unroll
                for (int nt = 0; nt < 4; nt++)
                    mma8(acc[mt][nt], af[mt], bf[nt]);
        }
        __syncthreads();
    }

#pragma unroll
    for (int mt = 0; mt < 2; mt++) {
        int r = bm + wm + mt * 16 + qid;
#pragma unroll
        for (int nt = 0; nt < 4; nt++) {
            int c0 = bn + wn + nt * 8 + 2 * qt;
            float b0 = bias[c0], b1 = bias[c0 + 1];
            *(float2*)&C[(size_t)r * N + c0] =
                make_float2(acc[mt][nt][0] + b0, acc[mt][nt][1] + b1);
            *(float2*)&C[(size_t)(r + 8) * N + c0] =
                make_float2(acc[mt][nt][2] + b0, acc[mt][nt][3] + b1);
        }
    }
}

// ---------------------------------------------------------------------------
// Flash attention, barrier-free groups.
// 1 block per (b,h), 256 threads = 8 warps = 4 groups x 2 warps.
// Group g streams 16-key chunks with c % 4 == g into its private double-
// buffered K/V smem (one 64-thread named barrier per chunk, no __syncthreads
// in main loop). Warp hw in group owns q-rows hw*16..+15; softmax fully
// in-register; P via warp-private smem tile (__syncwarp only).
// Per-warp online (m,l,acc) partials; 4-way combine at the end.
// ---------------------------------------------------------------------------
#define QPAD  132
#define KPADA 132   // (qid*132+qt) % 32 == 4*qid+qt -> conflict-free
#define VPADA 136   // (qt*136+qid) % 32 == 8*qt+qid -> conflict-free
#define PPITCH 20   // qid*20+qt perm mod 32 -> conflict-free

// float offsets in dynamic smem
#define SM_Q     0               // 32*132       = 4224
#define SM_KV    4224            // 4 groups * 8576 = 34304
#define GRP_SZ   8576            // K: 2*16*132 = 4224, V: 2*16*136 = 4352
#define GRP_V    4224
#define SM_P     38528           // 8 warps * 16*20 = 2560
#define SM_MS    41088           // 8*16
#define SM_LS    41216           // 8*16
#define SM_TOTAL 41344           // floats -> 165376 B

__global__ __launch_bounds__(256, 1) void attn_tf32(
    const float* __restrict__ qkv,   // (512, 6144) = (b*32+t, [q|k|v] h dk)
    const float* __restrict__ kc,    // (B,H,S,DK)
    const float* __restrict__ vc,
    float* __restrict__ o)           // (512, 2048)
{
    extern __shared__ float sm[];
    float* qs = sm + SM_Q;

    const int bh = blockIdx.x, b = bh >> 4, h = bh & 15;
    const int tid = threadIdx.x, w = tid >> 5, lane = tid & 31;
    const int qid = lane >> 2, qt = lane & 3;
    const int g = w >> 1, hw = w & 1;

    // load + scale q, tf32-round into smem
#pragma unroll
    for (int i = 0; i < 4; i++) {
        int id = tid + i * 256;
        int r = id >> 5, c = (id & 31) << 2;
        float4 v = *(const float4*)(qkv + (size_t)(b * 32 + r) * 6144 + h * 128 + c);
        qs[r * QPAD + c + 0] = __uint_as_float(f2tf(v.x * ATTN_SCALE));
        qs[r * QPAD + c + 1] = __uint_as_float(f2tf(v.y * ATTN_SCALE));
        qs[r * QPAD + c + 2] = __uint_as_float(f2tf(v.z * ATTN_SCALE));
        qs[r * QPAD + c + 3] = __uint_as_float(f2tf(v.w * ATTN_SCALE));
    }
    __syncthreads();

    // warp's Q rows (hw*16 .. +15) as A-fragments, K=128 -> 16 ks steps
    uint32_t qf[16][4];
    {
        const int rb = (hw * 16 + qid) * QPAD;
#pragma unroll
        for (int ks = 0; ks < 16; ks++) {
            int k0 = ks * 8;
            qf[ks][0] = __float_as_uint(qs[rb + k0 + qt]);
            qf[ks][1] = __float_as_uint(qs[rb + 8 * QPAD + k0 + qt]);
            qf[ks][2] = __float_as_uint(qs[rb + k0 + qt + 4]);
            qf[ks][3] = __float_as_uint(qs[rb + 8 * QPAD + k0 + qt + 4]);
        }
    }

    float acc[16][4];
#pragma unroll
    for (int i = 0; i < 16; i++)
#pragma unroll
        for (int j = 0; j < 4; j++) acc[i][j] = 0.f;
    float m0 = -1e30f, m1 = -1e30f, l0 = 0.f, l1 = 0.f;

    float* kv = sm + SM_KV + g * GRP_SZ;
    float* Pw = sm + SM_P + w * (16 * PPITCH);

    // chunk loader: each warp loads rows hw*8..+7 of K and V
    auto load = [&](int buf, int c) {
        float* kd = kv + buf * (16 * KPADA);
        float* vd = kv + GRP_V + buf * (16 * VPADA);
        if (c < 256) {
            const float* kp = kc + ((size_t)bh * 4096 + c * 16) * 128;
            const float* vp = vc + ((size_t)bh * 4096 + c * 16) * 128;
#pragma unroll
            for (int j = 0; j < 8; j++) {
                int r = hw * 8 + j;
                cpa16(&kd[r * KPADA + lane * 4], kp + r * 128 + lane * 4);
                cpa16(&vd[r * VPADA + lane * 4], vp + r * 128 + lane * 4);
            }
        } else {  // new K/V rows from qkv buffer
            int rn = (c - 256) * 16;
#pragma unroll
            for (int j = 0; j < 8; j++) {
                int r = hw * 8 + j;
                const float* base = qkv + (size_t)(b * 32 + rn + r) * 6144 + h * 128 + lane * 4;
                cpa16(&kd[r * KPADA + lane * 4], base + 2048);
                cpa16(&vd[r * VPADA + lane * 4], base + 4096);
            }
        }
        cp_commit();
    };

    const int niter = (261 - g) >> 2;  // 258 chunks of 16 keys, strided by 4
    load(0, g);
    for (int i = 0; i < niter; i++) {
        cp_wait<0>();
        asm volatile("bar.sync %0, %1;\n" :: "r"(g + 1), "r"(64));  // group barrier
        if (i + 1 < niter) load((i + 1) & 1, g + (i + 1) * 4);

        const float* kd = kv + (i & 1) * (16 * KPADA);
        const float* vd = kv + GRP_V + (i & 1) * (16 * VPADA);

        // ---- scores: 16 rows x 16 keys
        float sc[2][4];
        sc[0][0] = sc[0][1] = sc[0][2] = sc[0][3] = 0.f;
        sc[1][0] = sc[1][1] = sc[1][2] = sc[1][3] = 0.f;
#pragma unroll
        for (int ks = 0; ks < 16; ks++) {
            int k0 = ks * 8;
#pragma unroll
            for (int nt = 0; nt < 2; nt++) {
                uint32_t bf[2];
                bf[0] = f2tf(kd[(nt * 8 + qid) * KPADA + k0 + qt]);
                bf[1] = f2tf(kd[(nt * 8 + qid) * KPADA + k0 + qt + 4]);
                mma8(sc[nt], qf[ks], bf);
            }
        }

        // ---- in-register online softmax (rows qid and qid+8)
        float mx0 = fmaxf(fmaxf(sc[0][0], sc[0][1]), fmaxf(sc[1][0], sc[1][1]));
        float mx1 = fmaxf(fmaxf(sc[0][2], sc[0][3]), fmaxf(sc[1][2], sc[1][3]));
        mx0 = fmaxf(mx0, __shfl_xor_sync(0xffffffffu, mx0, 1));
        mx0 = fmaxf(mx0, __shfl_xor_sync(0xffffffffu, mx0, 2));
        mx1 = fmaxf(mx1, __shfl_xor_sync(0xffffffffu, mx1, 1));
        mx1 = fmaxf(mx1, __shfl_xor_sync(0xffffffffu, mx1, 2));
        float mn0 = fmaxf(m0, mx0), mn1 = fmaxf(m1, mx1);
        float c0 = __expf(m0 - mn0), c1 = __expf(m1 - mn1);
        float p00 = __expf(sc[0][0] - mn0), p01 = __expf(sc[0][1] - mn0);
        float p10 = __expf(sc[1][0] - mn0), p11 = __expf(sc[1][1] - mn0);
        float p02 = __expf(sc[0][2] - mn1), p03 = __expf(sc[0][3] - mn1);
        float p12 = __expf(sc[1][2] - mn1), p13 = __expf(sc[1][3] - mn1);
        float s0 = p00 + p01 + p10 + p11;
        float s1 = p02 + p03 + p12 + p13;
        s0 += __shfl_xor_sync(0xffffffffu, s0, 1);
        s0 += __shfl_xor_sync(0xffffffffu, s0, 2);
        s1 += __shfl_xor_sync(0xffffffffu, s1, 1);
        s1 += __shfl_xor_sync(0xffffffffu, s1, 2);
        l0 = l0 * c0 + s0; m0 = mn0;
        l1 = l1 * c1 + s1; m1 = mn1;

        // rescale accumulators
#pragma unroll
        for (int nt = 0; nt < 16; nt++) {
            acc[nt][0] *= c0; acc[nt][1] *= c0;
            acc[nt][2] *= c1; acc[nt][3] *= c1;
        }

        // ---- P -> warp-private smem (C-layout) -> A-fragments
        __syncwarp();  // prior iter's P loads done before overwrite
        *(float2*)&Pw[qid * PPITCH + 2 * qt] =
            make_float2(__uint_as_float(f2tf(p00)), __uint_as_float(f2tf(p01)));
        *(float2*)&Pw[qid * PPITCH + 8 + 2 * qt] =
            make_float2(__uint_as_float(f2tf(p10)), __uint_as_float(f2tf(p11)));
        *(float2*)&Pw[(qid + 8) * PPITCH + 2 * qt] =
            make_float2(__uint_as_float(f2tf(p02)), __uint_as_float(f2tf(p03)));
        *(float2*)&Pw[(qid + 8) * PPITCH + 8 + 2 * qt] =
            make_float2(__uint_as_float(f2tf(p12)), __uint_as_float(f2tf(p13)));
        __syncwarp();
        uint32_t pf[2][4];
#pragma unroll
        for (int k2 = 0; k2 < 2; k2++) {
            int k0 = k2 * 8;
            pf[k2][0] = __float_as_uint(Pw[qid * PPITCH + k0 + qt]);
            pf[k2][1] = __float_as_uint(Pw[(qid + 8) * PPITCH + k0 + qt]);
            pf[k2][2] = __float_as_uint(Pw[qid * PPITCH + k0 + qt + 4]);
            pf[k2][3] = __float_as_uint(Pw[(qid + 8) * PPITCH + k0 + qt + 4]);
        }

        // ---- P @ V : 16 rows x 128 d-cols
#pragma unroll
        for (int k2 = 0; k2 < 2; k2++) {
            int k0 = k2 * 8;
#pragma unroll
            for (int nt = 0; nt < 16; nt++) {
                uint32_t vf[2];
                vf[0] = f2tf(vd[(k0 + qt) * VPADA + nt * 8 + qid]);
                vf[1] = f2tf(vd[(k0 + qt + 4) * VPADA + nt * 8 + qid]);
                mma8(acc[nt], pf[k2], vf);
            }
        }
    }

    // ---- combine 4 group-partials per row half
    __syncthreads();  // all groups done; safe to alias KV region
    float* msS  = sm + SM_MS;
    float* lsS  = sm + SM_LS;
    float* accS = sm + SM_KV;  // 8 warps * 16 rows * 128 cols = 16384 floats

    if (qt == 0) {
        msS[w * 16 + qid] = m0;  msS[w * 16 + qid + 8] = m1;
        lsS[w * 16 + qid] = l0;  lsS[w * 16 + qid + 8] = l1;
    }
#pragma unroll
    for (int nt = 0; nt < 16; nt++) {
        *(float2*)&accS[w * 2048 + qid * 128 + nt * 8 + 2 * qt] =
            make_float2(acc[nt][0], acc[nt][1]);
        *(float2*)&accS[w * 2048 + (qid + 8) * 128 + nt * 8 + 2 * qt] =
            make_float2(acc[nt][2], acc[nt][3]);
    }
    __syncthreads();

    {
        int r = tid >> 3, cq = tid & 7;
        int hh = r >> 4, lr = r & 15;
        float mj[4], wj[4];
        float M = -1e30f;
#pragma unroll
        for (int j = 0; j < 4; j++) {
            mj[j] = msS[(2 * j + hh) * 16 + lr];
            M = fmaxf(M, mj[j]);
        }
        float L = 0.f;
#pragma unroll
        for (int j = 0; j < 4; j++) {
            wj[j] = __expf(mj[j] - M);
            L += wj[j] * lsS[(2 * j + hh) * 16 + lr];
        }
        float invL = 1.f / L;
#pragma unroll
        for (int cc = 0; cc < 4; cc++) {
            int col = cq * 16 + cc * 4;
            float4 s = make_float4(0.f, 0.f, 0.f, 0.f);
#pragma unroll
            for (int j = 0; j < 4; j++) {
                float4 a = *(float4*)&accS[(2 * j + hh) * 2048 + lr * 128 + col];
                s.x += wj[j] * a.x; s.y += wj[j] * a.y;
                s.z += wj[j] * a.z; s.w += wj[j] * a.w;
            }
            s.x *= invL; s.y *= invL; s.z *= invL; s.w *= invL;
            *(float4*)&o[(size_t)(b * 32 + r) * 2048 + h * 128 + col] = s;
        }
    }
}

// ---------------------------------------------------------------------------
// scratch + launch
// ---------------------------------------------------------------------------
__device__ float g_qkv[512 * 6144];
__device__ float g_attn[512 * 2048];

extern "C" void kernel_launch(void* const* d_in, const int* in_sizes, int n_in,
                              void* d_out, int out_size)
{
    const float* x    = (const float*)d_in[0];
    const float* kc   = (const float*)d_in[1];
    const float* vc   = (const float*)d_in[2];
    const float* qkvw = (const float*)d_in[3];
    const float* qkvb = (const float*)d_in[4];
    const float* outw = (const float*)d_in[5];
    const float* outb = (const float*)d_in[6];
    float* out = (float*)d_out;

    float *qkvbuf, *attnbuf;
    cudaGetSymbolAddress((void**)&qkvbuf, g_qkv);
    cudaGetSymbolAddress((void**)&attnbuf, g_attn);

    const int GEMM_SMEM = 2 * (64 + 128) * GPAD * sizeof(float);  // 55296 B
    const int ATTN_SMEM = SM_TOTAL * sizeof(float);               // 165376 B
    cudaFuncSetAttribute(gemm_tf32, cudaFuncAttributeMaxDynamicSharedMemorySize, GEMM_SMEM);
    cudaFuncSetAttribute(attn_tf32, cudaFuncAttributeMaxDynamicSharedMemorySize, ATTN_SMEM);

    // 1) fused QKV projection: (512x2048)@(6144x2048)^T + b
    gemm_tf32<<<dim3(48, 8), 256, GEMM_SMEM>>>(x, qkvw, qkvb, qkvbuf, 512, 6144, 2048);
    // 2) attention over cache + new kv
    attn_tf32<<<256, 256, ATTN_SMEM>>>(qkvbuf, kc, vc, attnbuf);
    // 3) output projection: (512x2048)@(2048x2048)^T + b
    gemm_tf32<<<dim3(16, 8), 256, GEMM_SMEM>>>(attnbuf, outw, outb, out, 512, 2048, 2048);
}